// round 7
// baseline (speedup 1.0000x reference)
#include <cuda_runtime.h>
#include <cuda_fp16.h>
#include <cstdint>

// ---------------------------------------------------------------------------
// Problem shape (fixed by the reference)
// ---------------------------------------------------------------------------
constexpr int M = 4096;      // B*S
constexpr int N = 16384;     // out_features
constexpr int K = 4096;      // in_features

// GEMM tiling
constexpr int BM = 128;
constexpr int BN = 256;
constexpr int BK = 64;                      // halves per k-tile = 128 B/row
constexpr int KT = K / BK;                  // 64 k-iterations
constexpr int STAGES = 4;

constexpr int A_BYTES = BM * 128;           // 16 KB
constexpr int B_BYTES = BN * 128;           // 32 KB
constexpr int STAGE_BYTES = A_BYTES + B_BYTES;        // 48 KB
constexpr int SMEM_TOTAL  = STAGES * STAGE_BYTES;     // 192 KB

// Scratch operand buffers (device globals: the sanctioned no-alloc scratch)
__device__ __align__(1024) __half g_XH[(size_t)M * K];   // fp16 X,   [M][K]
__device__ __align__(1024) __half g_WH[(size_t)N * K];   // deq W^T,  [N][K]
__device__ int g_w32;

// ---------------------------------------------------------------------------
// Pre-kernels
// ---------------------------------------------------------------------------
// Weight dtype detection (int8 vs sign-extended int32 delivery). R6 ncu
// confirmed int32 delivery, but keep both paths correct.
__global__ void detect_w_kernel(const unsigned char* __restrict__ w) {
    int all = 1;
    #pragma unroll
    for (int i = 0; i < 16; i++) {
        unsigned char b1 = w[4 * i + 1], b2 = w[4 * i + 2], b3 = w[4 * i + 3];
        int sext = (int)(((b1 == 0u) || (b1 == 0xFFu)) && (b2 == b1) && (b3 == b1));
        all &= sext;
    }
    g_w32 = all;
}

// X fp32 (holding exact fp16 values) -> fp16. Lossless.
__global__ void convert_x_kernel(const float4* __restrict__ X) {
    size_t i = (size_t)blockIdx.x * blockDim.x + threadIdx.x;   // < M*K/4
    float4 v = X[i];
    __half2* dst = reinterpret_cast<__half2*>(g_XH);
    dst[2 * i]     = __floats2half2_rn(v.x, v.y);
    dst[2 * i + 1] = __floats2half2_rn(v.z, v.w);
}

// Dequantize + transpose (int32 weight path, vectorized):
// WH[n][k] = fp16((W[k][n] + off[n]) * sc[n]).
// q+off exact in fp32, product exact in fp32, single fp16 rounding ->
// bit-identical to the reference's all-fp16 dequant (passed at 5.559e-5).
__global__ void dequant_w32_kernel(const int4* __restrict__ W32,
                                   const float4* __restrict__ sc4,
                                   const float4* __restrict__ off4) {
    if (g_w32 != 1) return;
    __shared__ __half tile[32][36];                      // [k][n], padded
    const int n0 = blockIdx.x * 32, k0 = blockIdx.y * 32;
    const int tx = threadIdx.x;                          // 0..7  (n/4 chunk)
    const int ty = threadIdx.y;                          // 0..31 (k row)
    const float4 s = sc4[(n0 >> 2) + tx];
    const float4 o = off4[(n0 >> 2) + tx];
    const int4 q = W32[((size_t)(k0 + ty) * N + n0) / 4 + tx];
    tile[ty][tx * 4 + 0] = __float2half_rn(((float)q.x + o.x) * s.x);
    tile[ty][tx * 4 + 1] = __float2half_rn(((float)q.y + o.y) * s.y);
    tile[ty][tx * 4 + 2] = __float2half_rn(((float)q.z + o.z) * s.z);
    tile[ty][tx * 4 + 3] = __float2half_rn(((float)q.w + o.w) * s.w);
    __syncthreads();
    // transposed write: thread (tx,ty) -> n = ty, k = tx*4..tx*4+3 (8B store)
    __half h[4];
    #pragma unroll
    for (int j = 0; j < 4; j++) h[j] = tile[tx * 4 + j][ty];
    *reinterpret_cast<uint2*>(&g_WH[(size_t)(n0 + ty) * K + k0 + tx * 4]) =
        *reinterpret_cast<const uint2*>(h);
}

// int8 weight path (fallback, scalar — correct if delivery is ever int8)
__global__ void dequant_w8_kernel(const int8_t* __restrict__ W8,
                                  const float* __restrict__ sc,
                                  const float* __restrict__ off) {
    if (g_w32 != 0) return;
    __shared__ __half tile[32][33];
    const int n0 = blockIdx.x * 32, k0 = blockIdx.y * 32;
    const int tx = threadIdx.x, ty = threadIdx.y;        // (32, 8)
    const float s = sc[n0 + tx], o = off[n0 + tx];
    #pragma unroll
    for (int j = 0; j < 4; j++) {
        const int k = k0 + ty + j * 8;
        int q = (int)W8[(size_t)k * N + n0 + tx];
        tile[ty + j * 8][tx] = __float2half_rn(((float)q + o) * s);
    }
    __syncthreads();
    #pragma unroll
    for (int j = 0; j < 4; j++) {
        const int n = n0 + ty + j * 8;
        g_WH[(size_t)n * K + k0 + tx] = tile[tx][ty + j * 8];
    }
}

// ---------------------------------------------------------------------------
// MMA helpers (baseline compute_103 PTX: ldmatrix + mma.sync HMMA)
// ---------------------------------------------------------------------------
__device__ __forceinline__ void ldsm4(uint32_t* r, uint32_t addr) {
    asm volatile("ldmatrix.sync.aligned.m8n8.x4.shared.b16 {%0,%1,%2,%3}, [%4];"
                 : "=r"(r[0]), "=r"(r[1]), "=r"(r[2]), "=r"(r[3]) : "r"(addr));
}
__device__ __forceinline__ void mma16816(float* c, const uint32_t* a,
                                         const uint32_t* b) {
    asm volatile(
        "mma.sync.aligned.m16n8k16.row.col.f32.f16.f16.f32 "
        "{%0,%1,%2,%3}, {%4,%5,%6,%7}, {%8,%9}, {%0,%1,%2,%3};"
        : "+f"(c[0]), "+f"(c[1]), "+f"(c[2]), "+f"(c[3])
        : "r"(a[0]), "r"(a[1]), "r"(a[2]), "r"(a[3]), "r"(b[0]), "r"(b[1]));
}

// ---------------------------------------------------------------------------
// GEMM: Out[BM x BN per CTA] = XH @ WH^T + bias, 4-stage cp.async pipeline,
// ONE __syncthreads per k-iter; next stage issued ahead of compute.
// ---------------------------------------------------------------------------
__global__ __launch_bounds__(256, 1)
void gemm_kernel(const float* __restrict__ Bias, float* __restrict__ Out)
{
    extern __shared__ __align__(1024) char smem[];
    const uint32_t sb = (uint32_t)__cvta_generic_to_shared(smem);
    const int tid  = threadIdx.x, lane = tid & 31, wid = tid >> 5;
    const int wm   = wid & 1;              // 2 m-slabs of 64 rows
    const int wn   = wid >> 1;             // 4 n-slabs of 64 cols
    const int bm   = blockIdx.x * BM;      // grid.x = 32 (m fastest -> L2 reuse)
    const int bn   = blockIdx.y * BN;

    // cp.async mapping: warp covers 4 rows x 8 chunks (16B) per pass
    const int lrow   = tid >> 3;           // 0..31
    const int lchunk = tid & 7;            // 0..7
    const __half* gA = g_XH + (size_t)(bm + lrow) * K + lchunk * 8;
    const __half* gB = g_WH + (size_t)(bn + lrow) * K + lchunk * 8;
    const int lsw = lchunk ^ (lrow & 7);   // swizzled chunk

    auto issue_stage = [&](int kt) {
        const int s = kt & (STAGES - 1);
        const uint32_t As = sb + s * STAGE_BYTES;
        const uint32_t Bs = As + A_BYTES;
        const int k0 = kt * BK;
        #pragma unroll
        for (int p = 0; p < 4; p++) {
            const uint32_t dst = As + (lrow + p * 32) * 128 + (lsw << 4);
            asm volatile("cp.async.cg.shared.global [%0], [%1], 16;"
                         :: "r"(dst), "l"(gA + (size_t)p * 32 * K + k0) : "memory");
        }
        #pragma unroll
        for (int p = 0; p < 8; p++) {
            const uint32_t dst = Bs + (lrow + p * 32) * 128 + (lsw << 4);
            asm volatile("cp.async.cg.shared.global [%0], [%1], 16;"
                         :: "r"(dst), "l"(gB + (size_t)p * 32 * K + k0) : "memory");
        }
        asm volatile("cp.async.commit_group;" ::: "memory");
    };

    // ldmatrix per-lane addressing constants
    const int g    = lane >> 3, lr7 = lane & 7;
    const int arow = wm * 64 + (g & 1) * 8 + lr7;   // + i*16
    const int acs  = g >> 1;                        // A chunk selector (0/1)
    const int brow = wn * 64 + (g >> 1) * 8 + lr7;  // + j*16
    const int bcs  = g & 1;                         // B chunk selector (0/1)
    const int arow7 = arow & 7, brow7 = brow & 7;

    float acc[4][8][4];
    #pragma unroll
    for (int i = 0; i < 4; i++)
        #pragma unroll
        for (int j = 0; j < 8; j++)
            #pragma unroll
            for (int c = 0; c < 4; c++)
                acc[i][j][c] = 0.0f;

    #pragma unroll
    for (int s = 0; s < STAGES - 1; s++) issue_stage(s);

    for (int kt = 0; kt < KT; kt++) {
        asm volatile("cp.async.wait_group %0;" :: "n"(STAGES - 2));
        __syncthreads();
        // Stage (kt+3)&3 == (kt-1)&3 was last read in iter kt-1; the barrier
        // above proves all warps are past it -> safe to overwrite now, and
        // the loads fly during this iteration's 128 MMAs.
        if (kt + STAGES - 1 < KT) issue_stage(kt + STAGES - 1);

        const int s = kt & (STAGES - 1);
        const uint32_t As = sb + s * STAGE_BYTES;
        const uint32_t Bs = As + A_BYTES;

        #pragma unroll
        for (int kk = 0; kk < 4; kk++) {          // 4 x k16 per k-tile
            const int ck = kk * 2;                // chunk base (8 halves/chunk)
            uint32_t af[4][4], bf[4][4];
            #pragma unroll
            for (int i = 0; i < 4; i++)
                ldsm4(af[i], As + (arow + i * 16) * 128 +
                             (((ck + acs) ^ arow7) << 4));
            #pragma unroll
            for (int j = 0; j < 4; j++)
                ldsm4(bf[j], Bs + (brow + j * 16) * 128 +
                             (((ck + bcs) ^ brow7) << 4));
            #pragma unroll
            for (int i = 0; i < 4; i++)
                #pragma unroll
                for (int jj = 0; jj < 8; jj++)
                    mma16816(acc[i][jj], af[i], &bf[jj >> 1][(jj & 1) * 2]);
        }
    }

    // Epilogue. Reference numerics: y = fp32( fp16(acc) + fp16(bias) ).
    const int r0  = lane >> 2;
    const int cof = (lane & 3) * 2;
    #pragma unroll
    for (int i = 0; i < 4; i++) {
        const int mrow = bm + wm * 64 + i * 16 + r0;
        #pragma unroll
        for (int jj = 0; jj < 8; jj++) {
            const int col = bn + wn * 64 + jj * 8 + cof;
            const __half b0 = __float2half_rn(__ldg(Bias + col));
            const __half b1 = __float2half_rn(__ldg(Bias + col + 1));
            float2 v0, v1;
            v0.x = __half2float(__hadd(__float2half_rn(acc[i][jj][0]), b0));
            v0.y = __half2float(__hadd(__float2half_rn(acc[i][jj][1]), b1));
            v1.x = __half2float(__hadd(__float2half_rn(acc[i][jj][2]), b0));
            v1.y = __half2float(__hadd(__float2half_rn(acc[i][jj][3]), b1));
            *reinterpret_cast<float2*>(Out + (size_t)mrow * N + col)       = v0;
            *reinterpret_cast<float2*>(Out + (size_t)(mrow + 8) * N + col) = v1;
        }
    }
}

// ---------------------------------------------------------------------------
// Host
// ---------------------------------------------------------------------------
extern "C" void kernel_launch(void* const* d_in, const int* in_sizes, int n_in,
                              void* d_out, int out_size)
{
    // metadata order: x, weight, weight_scale, weight_offset, bias
    const float* X    = (const float*)d_in[0];
    const void*  W    = d_in[1];
    const float* Wsc  = (const float*)d_in[2];
    const float* Woff = (const float*)d_in[3];
    const float* Bias = (const float*)d_in[4];
    float*       Out  = (float*)d_out;

    detect_w_kernel<<<1, 1>>>((const unsigned char*)W);
    convert_x_kernel<<<(int)((size_t)M * K / 4 / 256), 256>>>((const float4*)X);
    dequant_w32_kernel<<<dim3(N / 32, K / 32), dim3(8, 32)>>>(
        (const int4*)W, (const float4*)Wsc, (const float4*)Woff);
    dequant_w8_kernel<<<dim3(N / 32, K / 32), dim3(32, 8)>>>(
        (const int8_t*)W, Wsc, Woff);

    cudaFuncSetAttribute(gemm_kernel,
                         cudaFuncAttributeMaxDynamicSharedMemorySize, SMEM_TOTAL);
    gemm_kernel<<<dim3(M / BM, N / BN), 256, SMEM_TOTAL>>>(Bias, Out);
}

// round 8
// speedup vs baseline: 1.0251x; 1.0251x over previous
#include <cuda_runtime.h>
#include <cuda_fp16.h>
#include <cstdint>

// ---------------------------------------------------------------------------
// Problem shape (fixed by the reference)
// ---------------------------------------------------------------------------
constexpr int M = 4096;      // B*S
constexpr int N = 16384;     // out_features
constexpr int K = 4096;      // in_features

// GEMM tiling
constexpr int BM = 128;
constexpr int BN = 256;
constexpr int BK = 64;                      // halves per k-tile = 128 B/row
constexpr int KT = K / BK;                  // 64 k-iterations
constexpr int STAGES = 4;

constexpr int A_BYTES = BM * 128;           // 16 KB
constexpr int B_BYTES = BN * 128;           // 32 KB
constexpr int STAGE_BYTES = A_BYTES + B_BYTES;        // 48 KB
constexpr int SMEM_TOTAL  = STAGES * STAGE_BYTES;     // 192 KB

// Scratch operand buffers (device globals: the sanctioned no-alloc scratch)
__device__ __align__(1024) __half g_XH[(size_t)M * K];   // fp16 X,   [M][K]
__device__ __align__(1024) __half g_WH[(size_t)N * K];   // deq W^T,  [N][K]
__device__ int g_w32;

// ---------------------------------------------------------------------------
// Pre-kernels
// ---------------------------------------------------------------------------
// Weight dtype detection (int8 vs sign-extended int32 delivery). R6 ncu
// confirmed int32 delivery; both paths kept correct.
__global__ void detect_w_kernel(const unsigned char* __restrict__ w) {
    int all = 1;
    #pragma unroll
    for (int i = 0; i < 16; i++) {
        unsigned char b1 = w[4 * i + 1], b2 = w[4 * i + 2], b3 = w[4 * i + 3];
        int sext = (int)(((b1 == 0u) || (b1 == 0xFFu)) && (b2 == b1) && (b3 == b1));
        all &= sext;
    }
    g_w32 = all;
}

// X fp32 (holding exact fp16 values) -> fp16. Lossless.
__global__ void convert_x_kernel(const float4* __restrict__ X) {
    size_t i = (size_t)blockIdx.x * blockDim.x + threadIdx.x;   // < M*K/4
    float4 v = X[i];
    __half2* dst = reinterpret_cast<__half2*>(g_XH);
    dst[2 * i]     = __floats2half2_rn(v.x, v.y);
    dst[2 * i + 1] = __floats2half2_rn(v.z, v.w);
}

// Dequantize + transpose (int32 weight path, vectorized):
// WH[n][k] = fp16((W[k][n] + off[n]) * sc[n]).
// q+off exact in fp32, product exact in fp32, single fp16 rounding ->
// bit-identical to the reference's all-fp16 dequant (passes at 5.559e-5).
__global__ void dequant_w32_kernel(const int4* __restrict__ W32,
                                   const float4* __restrict__ sc4,
                                   const float4* __restrict__ off4) {
    if (g_w32 != 1) return;
    __shared__ __half tile[32][36];                      // [k][n], padded
    const int n0 = blockIdx.x * 32, k0 = blockIdx.y * 32;
    const int tx = threadIdx.x;                          // 0..7  (n/4 chunk)
    const int ty = threadIdx.y;                          // 0..31 (k row)
    const float4 s = sc4[(n0 >> 2) + tx];
    const float4 o = off4[(n0 >> 2) + tx];
    const int4 q = W32[((size_t)(k0 + ty) * N + n0) / 4 + tx];
    tile[ty][tx * 4 + 0] = __float2half_rn(((float)q.x + o.x) * s.x);
    tile[ty][tx * 4 + 1] = __float2half_rn(((float)q.y + o.y) * s.y);
    tile[ty][tx * 4 + 2] = __float2half_rn(((float)q.z + o.z) * s.z);
    tile[ty][tx * 4 + 3] = __float2half_rn(((float)q.w + o.w) * s.w);
    __syncthreads();
    __half h[4];
    #pragma unroll
    for (int j = 0; j < 4; j++) h[j] = tile[tx * 4 + j][ty];
    *reinterpret_cast<uint2*>(&g_WH[(size_t)(n0 + ty) * K + k0 + tx * 4]) =
        *reinterpret_cast<const uint2*>(h);
}

// int8 weight fallback: grid-stride so the DEAD launch (int32 delivery) costs
// ~2048 early-exit blocks instead of 65536 (saves ~34us/replay).
__global__ void dequant_w8_kernel(const int8_t* __restrict__ W8,
                                  const float* __restrict__ sc,
                                  const float* __restrict__ off) {
    if (g_w32 != 0) return;
    __shared__ __half tile[32][33];
    const int tx = threadIdx.x, ty = threadIdx.y;        // (32, 8)
    const int ntiles = (N / 32) * (K / 32);
    for (int t = blockIdx.x; t < ntiles; t += gridDim.x) {
        const int n0 = (t % (N / 32)) * 32, k0 = (t / (N / 32)) * 32;
        const float s = sc[n0 + tx], o = off[n0 + tx];
        #pragma unroll
        for (int j = 0; j < 4; j++) {
            const int k = k0 + ty + j * 8;
            int q = (int)W8[(size_t)k * N + n0 + tx];
            tile[ty + j * 8][tx] = __float2half_rn(((float)q + o) * s);
        }
        __syncthreads();
        #pragma unroll
        for (int j = 0; j < 4; j++) {
            const int n = n0 + ty + j * 8;
            g_WH[(size_t)n * K + k0 + tx] = tile[tx][ty + j * 8];
        }
        __syncthreads();
    }
}

// ---------------------------------------------------------------------------
// MMA helpers (baseline compute_103 PTX: ldmatrix + mma.sync HMMA)
// ---------------------------------------------------------------------------
__device__ __forceinline__ void ldsm4(uint32_t* r, uint32_t addr) {
    asm volatile("ldmatrix.sync.aligned.m8n8.x4.shared.b16 {%0,%1,%2,%3}, [%4];"
                 : "=r"(r[0]), "=r"(r[1]), "=r"(r[2]), "=r"(r[3]) : "r"(addr));
}
__device__ __forceinline__ void mma16816(float* c, const uint32_t* a,
                                         const uint32_t* b) {
    asm volatile(
        "mma.sync.aligned.m16n8k16.row.col.f32.f16.f16.f32 "
        "{%0,%1,%2,%3}, {%4,%5,%6,%7}, {%8,%9}, {%0,%1,%2,%3};"
        : "+f"(c[0]), "+f"(c[1]), "+f"(c[2]), "+f"(c[3])
        : "r"(a[0]), "r"(a[1]), "r"(a[2]), "r"(a[3]), "r"(b[0]), "r"(b[1]));
}

// ---------------------------------------------------------------------------
// GEMM: Out[BM x BN per CTA] = XH @ WH^T + bias. 4-stage cp.async pipeline,
// one barrier per k-iter, double-buffered ldmatrix fragments (prefetch kk+1
// during kk's 32 MMAs -> LDSM latency exposed once per k-tile, not 4x).
// ---------------------------------------------------------------------------
__global__ __launch_bounds__(256, 1)
void gemm_kernel(const float* __restrict__ Bias, float* __restrict__ Out)
{
    extern __shared__ __align__(1024) char smem[];
    const uint32_t sb = (uint32_t)__cvta_generic_to_shared(smem);
    const int tid  = threadIdx.x, lane = tid & 31, wid = tid >> 5;
    const int wm   = wid & 1;              // 2 m-slabs of 64 rows
    const int wn   = wid >> 1;             // 4 n-slabs of 64 cols
    const int bm   = blockIdx.x * BM;      // grid.x = 32 (m fastest -> L2 reuse)
    const int bn   = blockIdx.y * BN;

    // cp.async mapping: warp covers 4 rows x 8 chunks (16B) per pass
    const int lrow   = tid >> 3;           // 0..31
    const int lchunk = tid & 7;            // 0..7
    const __half* gA = g_XH + (size_t)(bm + lrow) * K + lchunk * 8;
    const __half* gB = g_WH + (size_t)(bn + lrow) * K + lchunk * 8;
    const int lsw = lchunk ^ (lrow & 7);   // swizzled chunk

    auto issue_stage = [&](int kt) {
        const int s = kt & (STAGES - 1);
        const uint32_t As = sb + s * STAGE_BYTES;
        const uint32_t Bs = As + A_BYTES;
        const int k0 = kt * BK;
        #pragma unroll
        for (int p = 0; p < 4; p++) {
            const uint32_t dst = As + (lrow + p * 32) * 128 + (lsw << 4);
            asm volatile("cp.async.cg.shared.global [%0], [%1], 16;"
                         :: "r"(dst), "l"(gA + (size_t)p * 32 * K + k0) : "memory");
        }
        #pragma unroll
        for (int p = 0; p < 8; p++) {
            const uint32_t dst = Bs + (lrow + p * 32) * 128 + (lsw << 4);
            asm volatile("cp.async.cg.shared.global [%0], [%1], 16;"
                         :: "r"(dst), "l"(gB + (size_t)p * 32 * K + k0) : "memory");
        }
        asm volatile("cp.async.commit_group;" ::: "memory");
    };

    // ldmatrix per-lane addressing constants
    const int g    = lane >> 3, lr7 = lane & 7;
    const int arow = wm * 64 + (g & 1) * 8 + lr7;   // + i*16
    const int acs  = g >> 1;                        // A chunk selector (0/1)
    const int brow = wn * 64 + (g >> 1) * 8 + lr7;  // + j*16
    const int bcs  = g & 1;                         // B chunk selector (0/1)
    const int arow7 = arow & 7, brow7 = brow & 7;

    float acc[4][8][4];
    #pragma unroll
    for (int i = 0; i < 4; i++)
        #pragma unroll
        for (int j = 0; j < 8; j++)
            #pragma unroll
            for (int c = 0; c < 4; c++)
                acc[i][j][c] = 0.0f;

    #pragma unroll
    for (int s = 0; s < STAGES - 1; s++) issue_stage(s);

    uint32_t af[2][4][4], bf[2][4][4];

    for (int kt = 0; kt < KT; kt++) {
        asm volatile("cp.async.wait_group %0;" :: "n"(STAGES - 2));
        __syncthreads();
        if (kt + STAGES - 1 < KT) issue_stage(kt + STAGES - 1);

        const int s = kt & (STAGES - 1);
        const uint32_t As = sb + s * STAGE_BYTES;
        const uint32_t Bs = As + A_BYTES;

        // Prefetch kk=0 fragments
        #pragma unroll
        for (int i = 0; i < 4; i++)
            ldsm4(af[0][i], As + (arow + i * 16) * 128 + ((acs ^ arow7) << 4));
        #pragma unroll
        for (int j = 0; j < 4; j++)
            ldsm4(bf[0][j], Bs + (brow + j * 16) * 128 + ((bcs ^ brow7) << 4));

        #pragma unroll
        for (int kk = 0; kk < 4; kk++) {
            const int cur = kk & 1, nxt = cur ^ 1;
            if (kk < 3) {
                const int ck = (kk + 1) * 2;
                #pragma unroll
                for (int i = 0; i < 4; i++)
                    ldsm4(af[nxt][i], As + (arow + i * 16) * 128 +
                                      (((ck + acs) ^ arow7) << 4));
                #pragma unroll
                for (int j = 0; j < 4; j++)
                    ldsm4(bf[nxt][j], Bs + (brow + j * 16) * 128 +
                                      (((ck + bcs) ^ brow7) << 4));
            }
            #pragma unroll
            for (int i = 0; i < 4; i++)
                #pragma unroll
                for (int jj = 0; jj < 8; jj++)
                    mma16816(acc[i][jj], af[cur][i], &bf[cur][jj >> 1][(jj & 1) * 2]);
        }
    }

    // Epilogue. Reference numerics: y = fp32( fp16(acc) + fp16(bias) ).
    const int r0  = lane >> 2;
    const int cof = (lane & 3) * 2;
    #pragma unroll
    for (int i = 0; i < 4; i++) {
        const int mrow = bm + wm * 64 + i * 16 + r0;
        #pragma unroll
        for (int jj = 0; jj < 8; jj++) {
            const int col = bn + wn * 64 + jj * 8 + cof;
            const __half b0 = __float2half_rn(__ldg(Bias + col));
            const __half b1 = __float2half_rn(__ldg(Bias + col + 1));
            float2 v0, v1;
            v0.x = __half2float(__hadd(__float2half_rn(acc[i][jj][0]), b0));
            v0.y = __half2float(__hadd(__float2half_rn(acc[i][jj][1]), b1));
            v1.x = __half2float(__hadd(__float2half_rn(acc[i][jj][2]), b0));
            v1.y = __half2float(__hadd(__float2half_rn(acc[i][jj][3]), b1));
            *reinterpret_cast<float2*>(Out + (size_t)mrow * N + col)       = v0;
            *reinterpret_cast<float2*>(Out + (size_t)(mrow + 8) * N + col) = v1;
        }
    }
}

// ---------------------------------------------------------------------------
// Host
// ---------------------------------------------------------------------------
extern "C" void kernel_launch(void* const* d_in, const int* in_sizes, int n_in,
                              void* d_out, int out_size)
{
    // metadata order: x, weight, weight_scale, weight_offset, bias
    const float* X    = (const float*)d_in[0];
    const void*  W    = d_in[1];
    const float* Wsc  = (const float*)d_in[2];
    const float* Woff = (const float*)d_in[3];
    const float* Bias = (const float*)d_in[4];
    float*       Out  = (float*)d_out;

    detect_w_kernel<<<1, 1>>>((const unsigned char*)W);
    convert_x_kernel<<<(int)((size_t)M * K / 4 / 256), 256>>>((const float4*)X);
    dequant_w32_kernel<<<dim3(N / 32, K / 32), dim3(8, 32)>>>(
        (const int4*)W, (const float4*)Wsc, (const float4*)Woff);
    dequant_w8_kernel<<<2048, dim3(32, 8)>>>((const int8_t*)W, Wsc, Woff);

    cudaFuncSetAttribute(gemm_kernel,
                         cudaFuncAttributeMaxDynamicSharedMemorySize, SMEM_TOTAL);
    gemm_kernel<<<dim3(M / BM, N / BN), 256, SMEM_TOTAL>>>(Bias, Out);
}